// round 2
// baseline (speedup 1.0000x reference)
#include <cuda_runtime.h>

// S5 associative scan: (A_i,Bu_i)*(A_j,Bu_j) = (A_j*A_i, A_j*Bu_i + Bu_j)
// Per channel d: inclusive scan over t of first-order recurrence.
//   Acum_t = A_t * Acum_{t-1}            (Acum_{-1} = 1)
//   S_t    = A_t * S_{t-1} + Bu_t        (S_{-1}    = 0)
// Output layout: out[0 : T*D] = A_scan, out[T*D : 2*T*D] = Bu_scan.

#define TT 131072
#define DD 256
#define GG 512              // number of time chunks
#define LL (TT / GG)        // 256 rows per chunk

// Scratch: per-chunk aggregates and exclusive prefixes (static device arrays —
// no allocations allowed in kernel_launch).
__device__ float g_aggA[GG * DD];
__device__ float g_aggS[GG * DD];
__device__ float g_prefA[GG * DD];
__device__ float g_prefS[GG * DD];

// Pass 1: each block scans its chunk, emits per-channel aggregate
// (product of A over chunk, chunk-local final S).
__global__ __launch_bounds__(DD) void s5_pass1(const float* __restrict__ A,
                                               const float* __restrict__ Bu) {
    const int c = blockIdx.x;
    const int d = threadIdx.x;
    const size_t base = (size_t)c * LL * DD + d;

    float aA = 1.0f;
    float s  = 0.0f;
#pragma unroll 8
    for (int t = 0; t < LL; ++t) {
        const size_t idx = base + (size_t)t * DD;
        const float a  = __ldg(&A[idx]);
        const float bu = __ldg(&Bu[idx]);
        aA = aA * a;
        s  = fmaf(a, s, bu);
    }
    g_aggA[c * DD + d] = aA;
    g_aggS[c * DD + d] = s;
}

// Pass 2: one block; thread d sequentially scans the G chunk aggregates for
// channel d, writing the EXCLUSIVE prefix for each chunk.
__global__ __launch_bounds__(DD) void s5_pass2() {
    const int d = threadIdx.x;
    float pA = 1.0f;
    float pS = 0.0f;
#pragma unroll 4
    for (int c = 0; c < GG; ++c) {
        g_prefA[c * DD + d] = pA;
        g_prefS[c * DD + d] = pS;
        const float a = g_aggA[c * DD + d];
        const float s = g_aggS[c * DD + d];
        pS = fmaf(a, pS, s);
        pA = pA * a;
    }
}

// Pass 3: rescan each chunk seeded with the exclusive prefix; write outputs.
__global__ __launch_bounds__(DD) void s5_pass3(const float* __restrict__ A,
                                               const float* __restrict__ Bu,
                                               float* __restrict__ outA,
                                               float* __restrict__ outS) {
    const int c = blockIdx.x;
    const int d = threadIdx.x;
    const size_t base = (size_t)c * LL * DD + d;

    float aA = g_prefA[c * DD + d];
    float s  = g_prefS[c * DD + d];
#pragma unroll 8
    for (int t = 0; t < LL; ++t) {
        const size_t idx = base + (size_t)t * DD;
        const float a  = __ldg(&A[idx]);
        const float bu = __ldg(&Bu[idx]);
        aA = aA * a;
        s  = fmaf(a, s, bu);
        outA[idx] = aA;
        outS[idx] = s;
    }
}

extern "C" void kernel_launch(void* const* d_in, const int* in_sizes, int n_in,
                              void* d_out, int out_size) {
    const float* A  = (const float*)d_in[0];
    const float* Bu = (const float*)d_in[1];
    float* outA = (float*)d_out;
    float* outS = (float*)d_out + (size_t)TT * DD;

    s5_pass1<<<GG, DD>>>(A, Bu);
    s5_pass2<<<1, DD>>>();
    s5_pass3<<<GG, DD>>>(A, Bu, outA, outS);
}